// round 12
// baseline (speedup 1.0000x reference)
#include <cuda_runtime.h>
#include <cuda_fp16.h>
#include <cstdint>

// Problem constants (fixed shapes from reference)
#define BATCH   4
#define NPIX    4096          // H*W = 64*64
#define CCH     256
#define GRP     8
#define GSIZE   32            // CCH / GRP
#define MALL    16384         // BATCH * NPIX

// -------- scratch (static device globals; no allocation) --------
__device__ float g_ps [32 * 8];                           // GN partial sums
__device__ float g_ps2[32 * 8];                           // GN partial sumsq
__device__ float g_mean[BATCH * GRP];
__device__ float g_rstd[BATCH * GRP];
__device__ __half g_xnh[MALL * CCH];
__device__ __half g_qkh[2 * MALL * CCH];                  // Q then K (fp16)
__device__ __half g_vth[CCH * MALL];                      // V2 transposed (fp16): [256][16384]
__device__ __half g_sh[(long long)BATCH * NPIX * NPIX];   // exp'd scores, fp16 (128 MB)
__device__ __half g_wTh[3 * CCH * CCH];                   // wq^T, wk^T, wvp^T (fp16)
__device__ float g_bvp[CCH];                              // bv @ wp + bp
__device__ float g_Lp[64 * MALL];                         // row-sum partials [64][16384]
__device__ float g_inv[MALL];                             // 1 / rowsum

// ---------------- GroupNorm partial stats: one block per (bg, slice) ----------------
__global__ void gn_part(const float* __restrict__ x) {
    int bg = blockIdx.x;            // 0..31
    int sl = blockIdx.y;            // 0..7
    int b = bg >> 3, g = bg & 7;
    const float* base = x + (long)b * NPIX * CCH + g * GSIZE;
    float s = 0.f, ss = 0.f;
    for (int i = threadIdx.x; i < 512 * GSIZE; i += blockDim.x) {
        int p = sl * 512 + (i >> 5), c = i & 31;
        float v = base[(long)p * CCH + c];
        s += v; ss += v * v;
    }
    __shared__ float sh[16];
    #pragma unroll
    for (int o = 16; o > 0; o >>= 1) {
        s  += __shfl_xor_sync(0xffffffffu, s,  o);
        ss += __shfl_xor_sync(0xffffffffu, ss, o);
    }
    int w = threadIdx.x >> 5, l = threadIdx.x & 31;
    if (l == 0) { sh[w] = s; sh[8 + w] = ss; }
    __syncthreads();
    if (threadIdx.x == 0) {
        float S = 0.f, SS = 0.f;
        #pragma unroll
        for (int i = 0; i < 8; i++) { S += sh[i]; SS += sh[8 + i]; }
        g_ps [bg * 8 + sl] = S;
        g_ps2[bg * 8 + sl] = SS;
    }
}
__global__ void gn_final() {
    int bg = threadIdx.x;   // 32 threads
    float S = 0.f, SS = 0.f;
    #pragma unroll
    for (int i = 0; i < 8; i++) { S += g_ps[bg * 8 + i]; SS += g_ps2[bg * 8 + i]; }
    const float invn = 1.0f / (NPIX * GSIZE);
    float mean = S * invn;
    float var  = SS * invn - mean * mean;
    g_mean[bg] = mean;
    g_rstd[bg] = rsqrtf(var + 1e-3f);
}

// ---------------- GroupNorm apply: fp32 in, fp16 out ----------------
__global__ void gn_apply(const float* __restrict__ x,
                         const float* __restrict__ gamma,
                         const float* __restrict__ beta) {
    long i4 = (long)blockIdx.x * blockDim.x + threadIdx.x;   // float4 index
    float4 xv = ((const float4*)x)[i4];
    int c0 = (int)(i4 & 63) * 4;        // 64 float4 per channel row
    long row = i4 >> 6;                 // pixel index 0..16383
    int b = (int)(row >> 12);           // /4096
    int bg = b * 8 + (c0 >> 5);
    float m = g_mean[bg], r = g_rstd[bg];
    __half2 h0 = __floats2half2_rn((xv.x - m) * r * gamma[c0 + 0] + beta[c0 + 0],
                                   (xv.y - m) * r * gamma[c0 + 1] + beta[c0 + 1]);
    __half2 h1 = __floats2half2_rn((xv.z - m) * r * gamma[c0 + 2] + beta[c0 + 2],
                                   (xv.w - m) * r * gamma[c0 + 3] + beta[c0 + 3]);
    uint2 pk; pk.x = *(unsigned*)&h0; pk.y = *(unsigned*)&h1;
    ((uint2*)g_xnh)[i4] = pk;
}

// ---------------- transpose wq, wk into fp16 ----------------
__global__ void transpose_w(const float* __restrict__ wq, const float* __restrict__ wk) {
    __shared__ float t[32][33];
    int mat = blockIdx.z;
    const float* src = (mat == 0) ? wq : wk;
    int x0 = blockIdx.x * 32, y0 = blockIdx.y * 32;
    t[threadIdx.y][threadIdx.x] = src[(y0 + threadIdx.y) * CCH + x0 + threadIdx.x];
    __syncthreads();
    g_wTh[mat * CCH * CCH + (x0 + threadIdx.y) * CCH + y0 + threadIdx.x] =
        __float2half_rn(t[threadIdx.x][threadIdx.y]);
}

// ---------------- wvp^T = (wv @ wp)^T in fp16 (fp32 accumulation) ----------------
__global__ void wvp_gemm(const float* __restrict__ wv, const float* __restrict__ wp) {
    __shared__ float a[32][33], b[32][33];
    int bx = blockIdx.x, by = blockIdx.y;
    int tx = threadIdx.x, ty = threadIdx.y;
    float acc = 0.f;
    for (int k0 = 0; k0 < CCH; k0 += 32) {
        a[ty][tx] = wv[(by * 32 + ty) * CCH + k0 + tx];
        b[ty][tx] = wp[(k0 + ty) * CCH + bx * 32 + tx];
        __syncthreads();
        #pragma unroll
        for (int k = 0; k < 32; k++) acc += a[ty][k] * b[k][tx];
        __syncthreads();
    }
    // D[y,x] = (wv@wp)[y,x]; store transposed into slot 2
    g_wTh[2 * CCH * CCH + (bx * 32 + tx) * CCH + by * 32 + ty] = __float2half_rn(acc);
}

// ---------------- bvp = bv @ wp + bp ----------------
__global__ void bvp_k(const float* __restrict__ bv, const float* __restrict__ wp,
                      const float* __restrict__ bp) {
    int c = threadIdx.x;   // 256 threads
    float s = bp[c];
    for (int k = 0; k < CCH; k++) s += bv[k] * wp[k * CCH + c];
    g_bvp[c] = s;
}

// ---------------- cp.async / mma / ldmatrix helpers ----------------
__device__ __forceinline__ void cp16g(void* smem, const void* gmem) {
    unsigned s = (unsigned)__cvta_generic_to_shared(smem);
    asm volatile("cp.async.cg.shared.global [%0], [%1], 16;\n" :: "r"(s), "l"(gmem));
}
__device__ __forceinline__ void cp_commit() { asm volatile("cp.async.commit_group;\n"); }
__device__ __forceinline__ void cp_wait0() { asm volatile("cp.async.wait_group 0;\n"); }
__device__ __forceinline__ void cp_wait1() { asm volatile("cp.async.wait_group 1;\n"); }

__device__ __forceinline__ void mma_f16(float* c, const unsigned* a, const unsigned* b) {
    asm volatile("mma.sync.aligned.m16n8k16.row.col.f32.f16.f16.f32 "
        "{%0,%1,%2,%3}, {%4,%5,%6,%7}, {%8,%9}, {%0,%1,%2,%3};"
        : "+f"(c[0]), "+f"(c[1]), "+f"(c[2]), "+f"(c[3])
        : "r"(a[0]), "r"(a[1]), "r"(a[2]), "r"(a[3]), "r"(b[0]), "r"(b[1]));
}
__device__ __forceinline__ void ldsm4(unsigned* r, uint32_t addr) {
    asm volatile("ldmatrix.sync.aligned.m8n8.x4.shared.b16 {%0,%1,%2,%3}, [%4];"
        : "=r"(r[0]), "=r"(r[1]), "=r"(r[2]), "=r"(r[3]) : "r"(addr));
}

// ================= unified fp16 GEMM: C = f(A @ B^T), CTA 128x128, warp 32x64 =================
// A: [M,K] halves lda, B: [N,K] halves ldb (dot over K). Batched via blockIdx.z.
// K-slab = 64 halves, smem pitch 72 halves, 3-stage cp.async pipeline, one bar/slab.
// EPI 0: C(half)  = acc + bias[col]; bias = biasc (z=0) or biasr (z=1)   (Q & K merged)
// EPI 1: C(half)  = acc                                                  (V2T projection)
// EPI 2: C(half)  = exp(alpha*acc); Lp partial row sums                  (scores)
// EPI 3: C(float) = acc * inv[row] + biasc[col] + resid[off]             (attn@V2 -> out)
#define HP 72                       // smem pitch in halves (64 data + 8 pad)
#define SSH (128 * HP)              // halves per matrix per stage (9216)
template<int EPI>
__global__ void __launch_bounds__(256, 2)
hgemm(const __half* __restrict__ A, int lda, long long sAz,
      const __half* __restrict__ B, int ldb, long long sBz,
      void* __restrict__ Cv, int ldc, long long sCz,
      const float* __restrict__ biasc, const float* __restrict__ biasr,
      const float* __restrict__ resid,
      float* __restrict__ Lp, const float* __restrict__ inv,
      float alpha, int K)
{
    extern __shared__ __align__(16) __half dsm[];   // [3][A:SSH | B:SSH]

    A += (long long)blockIdx.z * sAz;
    B += (long long)blockIdx.z * sBz;

    const int tid = threadIdx.x;
    const int w = tid >> 5, lane = tid & 31;
    const int gid = lane >> 2, tig = lane & 3;
    const int wm = (w & 3) * 32;        // 4 m-warps
    const int wn = (w >> 2) * 64;       // 2 n-warps
    const int wg = w >> 2;
    const long long m0 = (long long)blockIdx.y * 128;
    const long long n0 = (long long)blockIdx.x * 128;

    // loader coords: each thread copies 4x16B per matrix per stage
    const int lr = tid >> 1;            // row 0..127
    const int lc = (tid & 1) * 32;      // half-offset 0 or 32
    const __half* Ag = A + (m0 + lr) * lda + lc;
    const __half* Bg = B + (n0 + lr) * (long long)ldb + lc;
    __half* Asd = dsm + lr * HP + lc;   // stage 0 A dst

    // ldmatrix lane address components (in halves)
    const int a_row = wm + (lane & 15);
    const int a_col = (lane >> 4) << 3;
    const int b_row = wn + ((lane >> 4) << 3) + (lane & 7);
    const int b_col = ((lane >> 3) & 1) << 3;
    const uint32_t smB = (uint32_t)__cvta_generic_to_shared(dsm);

    float acc[2][8][4] = {};
    const int KT = K >> 6;              // slabs of 64 halves

    // prologue: slab 0 -> stage 0, slab 1 -> stage 1
    #pragma unroll
    for (int j = 0; j < 4; j++) { cp16g(Asd + 8 * j, Ag + 8 * j); }
    #pragma unroll
    for (int j = 0; j < 4; j++) { cp16g(Asd + SSH + 8 * j, Bg + 8 * j); }
    cp_commit();
    {
        __half* ad = Asd + 2 * SSH;
        #pragma unroll
        for (int j = 0; j < 4; j++) { cp16g(ad + 8 * j, Ag + 64 + 8 * j); }
        #pragma unroll
        for (int j = 0; j < 4; j++) { cp16g(ad + SSH + 8 * j, Bg + 64 + 8 * j); }
        cp_commit();
    }

    int sc = 0;                          // current stage = kt % 3
    for (int kt = 0; kt < KT; kt++) {
        if (kt + 1 < KT) cp_wait1(); else cp_wait0();
        __syncthreads();                 // stage sc ready; stage (kt+2)%3 free
        if (kt + 2 < KT) {
            int s2 = sc + 2; if (s2 >= 3) s2 -= 3;
            long long ko = (long long)(kt + 2) * 64;
            __half* ad = Asd + s2 * (2 * SSH);
            #pragma unroll
            for (int j = 0; j < 4; j++) { cp16g(ad + 8 * j, Ag + ko + 8 * j); }
            #pragma unroll
            for (int j = 0; j < 4; j++) { cp16g(ad + SSH + 8 * j, Bg + ko + 8 * j); }
            cp_commit();
        }
        const uint32_t asb = smB + sc * (4 * SSH);
        const uint32_t bsb = asb + 2 * SSH;
        #pragma unroll
        for (int kk = 0; kk < 64; kk += 16) {
            unsigned a[2][4], b[4][4];
            #pragma unroll
            for (int mt = 0; mt < 2; mt++)
                ldsm4(a[mt], asb + ((a_row + mt * 16) * HP + kk + a_col) * 2);
            #pragma unroll
            for (int p = 0; p < 4; p++)
                ldsm4(b[p], bsb + ((b_row + p * 16) * HP + kk + b_col) * 2);
            #pragma unroll
            for (int mt = 0; mt < 2; mt++)
                #pragma unroll
                for (int nt = 0; nt < 8; nt++)
                    mma_f16(acc[mt][nt], a[mt], &b[nt >> 1][(nt & 1) * 2]);
        }
        if (++sc == 3) sc = 0;
    }

    // ---------------- epilogue ----------------
    #pragma unroll
    for (int mt = 0; mt < 2; mt++) {
        #pragma unroll
        for (int h = 0; h < 2; h++) {
            long long row = m0 + wm + mt * 16 + gid + 8 * h;
            long long cbase = row * ldc + n0 + wn + 2 * tig;
            if (EPI == 2) {
                __half* C = (__half*)Cv + (long long)blockIdx.z * sCz;
                float rowsum = 0.f;
                #pragma unroll
                for (int nt = 0; nt < 8; nt++) {
                    float v0 = __expf(acc[mt][nt][2 * h]     * alpha);
                    float v1 = __expf(acc[mt][nt][2 * h + 1] * alpha);
                    rowsum += v0 + v1;
                    *(__half2*)&C[cbase + nt * 8] = __floats2half2_rn(v0, v1);
                }
                rowsum += __shfl_xor_sync(0xffffffffu, rowsum, 1);
                rowsum += __shfl_xor_sync(0xffffffffu, rowsum, 2);
                if (tig == 0)
                    Lp[(blockIdx.x * 2 + wg) * (long long)MALL
                       + blockIdx.z * (long long)NPIX + row] = rowsum;
            } else if (EPI == 3) {
                float* C = (float*)Cv + (long long)blockIdx.z * sCz;
                const float* R = resid + (long long)blockIdx.z * sCz;
                float rs = inv[blockIdx.z * (long long)NPIX + row];
                #pragma unroll
                for (int nt = 0; nt < 8; nt++) {
                    long long c0 = n0 + wn + nt * 8 + 2 * tig;
                    long long off = cbase + nt * 8;
                    float v0 = acc[mt][nt][2 * h]     * rs + biasc[c0]     + R[off];
                    float v1 = acc[mt][nt][2 * h + 1] * rs + biasc[c0 + 1] + R[off + 1];
                    *(float2*)&C[off] = make_float2(v0, v1);
                }
            } else if (EPI == 0) {
                __half* C = (__half*)Cv + (long long)blockIdx.z * sCz;
                const float* bc = blockIdx.z ? biasr : biasc;   // biasr slot carries bk
                #pragma unroll
                for (int nt = 0; nt < 8; nt++) {
                    long long c0 = n0 + wn + nt * 8 + 2 * tig;
                    *(__half2*)&C[cbase + nt * 8] =
                        __floats2half2_rn(acc[mt][nt][2 * h] + bc[c0],
                                          acc[mt][nt][2 * h + 1] + bc[c0 + 1]);
                }
            } else {  // EPI 1: plain fp16 store (V2 bias folded into bvp)
                __half* C = (__half*)Cv;
                #pragma unroll
                for (int nt = 0; nt < 8; nt++)
                    *(__half2*)&C[cbase + nt * 8] =
                        __floats2half2_rn(acc[mt][nt][2 * h],
                                          acc[mt][nt][2 * h + 1]);
            }
        }
    }
}

// ---------------- rowsum inverse: inv[i] = 1 / sum_j Lp[j][i] ----------------
__global__ void rowsum_inv(const float* __restrict__ Lp, float* __restrict__ inv) {
    int i = blockIdx.x * 256 + threadIdx.x;
    float s = 0.f;
    #pragma unroll
    for (int j = 0; j < 64; j++) s += Lp[j * MALL + i];
    inv[i] = 1.0f / s;
}

// ---------------- launch ----------------
extern "C" void kernel_launch(void* const* d_in, const int* in_sizes, int n_in,
                              void* d_out, int out_size) {
    const float* x     = (const float*)d_in[0];
    const float* gamma = (const float*)d_in[1];
    const float* beta  = (const float*)d_in[2];
    const float* wq    = (const float*)d_in[3];
    const float* bq    = (const float*)d_in[4];
    const float* wk    = (const float*)d_in[5];
    const float* bk    = (const float*)d_in[6];
    const float* wv    = (const float*)d_in[7];
    const float* bv    = (const float*)d_in[8];
    const float* wp    = (const float*)d_in[9];
    const float* bp    = (const float*)d_in[10];
    float* out = (float*)d_out;

    float *Lp, *inv, *bvp;
    __half *xnh, *qkh, *vth, *sh, *wTh;
    cudaGetSymbolAddress((void**)&xnh, g_xnh);
    cudaGetSymbolAddress((void**)&qkh, g_qkh);
    cudaGetSymbolAddress((void**)&vth, g_vth);
    cudaGetSymbolAddress((void**)&sh,  g_sh);
    cudaGetSymbolAddress((void**)&wTh, g_wTh);
    cudaGetSymbolAddress((void**)&Lp,  g_Lp);
    cudaGetSymbolAddress((void**)&inv, g_inv);
    cudaGetSymbolAddress((void**)&bvp, g_bvp);
    __half* qh = qkh;
    __half* kh = qkh + (long long)MALL * CCH;

    const int SMB = 3 * 2 * SSH * 2;   // 110,592 B dynamic smem (occ 2 = 221 KB/SM)
    cudaFuncSetAttribute(hgemm<0>, cudaFuncAttributeMaxDynamicSharedMemorySize, SMB);
    cudaFuncSetAttribute(hgemm<1>, cudaFuncAttributeMaxDynamicSharedMemorySize, SMB);
    cudaFuncSetAttribute(hgemm<2>, cudaFuncAttributeMaxDynamicSharedMemorySize, SMB);
    cudaFuncSetAttribute(hgemm<3>, cudaFuncAttributeMaxDynamicSharedMemorySize, SMB);

    // 1. GroupNorm -> fp16 xn
    gn_part<<<dim3(BATCH * GRP, 8), 256>>>(x);
    gn_final<<<1, 32>>>();
    gn_apply<<<(MALL * CCH / 4) / 256, 256>>>(x, gamma, beta);

    // 2. weight prep: wq^T, wk^T (fp16); wvp^T = (wv@wp)^T (fp16); bvp
    transpose_w<<<dim3(8, 8, 2), dim3(32, 32)>>>(wq, wk);
    wvp_gemm<<<dim3(8, 8), dim3(32, 32)>>>(wv, wp);
    bvp_k<<<1, 256>>>(bv, wp, bp);

    // 3. Q & K (merged, grid.z selects), V2T = wvp^T x xn^T (produced transposed)
    hgemm<0><<<dim3(2, 128, 2), 256, SMB>>>(
        xnh, CCH, 0, wTh, CCH, (long long)CCH * CCH, qkh, CCH, (long long)MALL * CCH,
        bq, bk, nullptr, nullptr, nullptr, 1.0f, CCH);
    hgemm<1><<<dim3(MALL / 128, CCH / 128, 1), 256, SMB>>>(
        wTh + 2 * CCH * CCH, CCH, 0, xnh, CCH, 0, vth, MALL, 0,
        nullptr, nullptr, nullptr, nullptr, nullptr, 1.0f, CCH);

    // 4. S = exp(Q @ K^T / 16) in fp16, plus row-sum partials
    hgemm<2><<<dim3(NPIX / 128, NPIX / 128, BATCH), 256, SMB>>>(
        qh, CCH, (long long)NPIX * CCH,
        kh, CCH, (long long)NPIX * CCH,
        sh, NPIX, (long long)NPIX * NPIX,
        nullptr, nullptr, nullptr, Lp, nullptr, 0.0625f, CCH);

    // 5. inv[row] = 1 / rowsum
    rowsum_inv<<<MALL / 256, 256>>>(Lp, inv);

    // 6. out = x + (S @ V2) * inv + bvp    (K = 4096; writes final output directly)
    hgemm<3><<<dim3(CCH / 128, NPIX / 128, BATCH), 256, SMB>>>(
        sh, NPIX, (long long)NPIX * NPIX,
        vth, MALL, (long long)NPIX,
        out, CCH, (long long)NPIX * CCH,
        bvp, nullptr, x, nullptr, inv, 1.0f, NPIX);
}

// round 15
// speedup vs baseline: 1.0278x; 1.0278x over previous
#include <cuda_runtime.h>
#include <cuda_fp16.h>
#include <cstdint>

// Problem constants (fixed shapes from reference)
#define BATCH   4
#define NPIX    4096          // H*W = 64*64
#define CCH     256
#define GRP     8
#define GSIZE   32            // CCH / GRP
#define MALL    16384         // BATCH * NPIX

// -------- scratch (static device globals; no allocation) --------
__device__ float g_ps [32 * 8];                           // GN partial sums
__device__ float g_ps2[32 * 8];                           // GN partial sumsq
__device__ __half g_xnh[MALL * CCH];
__device__ __half g_qkh[2 * MALL * CCH];                  // Q then K (fp16)
__device__ __half g_vth[CCH * MALL];                      // V transposed (fp16): [256][16384]
__device__ __half g_oh[MALL * CCH];                       // attention output (fp16)
__device__ __half g_sh[(long long)BATCH * NPIX * NPIX];   // exp'd scores, fp16 (128 MB)
__device__ __half g_wTh[4 * CCH * CCH];                   // wq^T, wk^T, wv^T, wp^T (fp16)
__device__ float g_Lp[(long long)MALL * 64];              // row-sum partials [16384][64]
__device__ float g_inv[MALL];                             // 1 / rowsum

// ---------------- combined prep: GN partial stats + weight transposes ----------------
// blocks 0..255:  GN partials for (bg = id>>3, slice = id&7)
// blocks 256..511: 32x32 transpose tiles of the four weight matrices -> fp16
__global__ void gnprep(const float* __restrict__ x,
                       const float* __restrict__ wq, const float* __restrict__ wk,
                       const float* __restrict__ wv, const float* __restrict__ wp) {
    __shared__ float t[32][33];
    int id = blockIdx.x;
    int tid = threadIdx.x;
    if (id < 256) {
        int bg = id >> 3, sl = id & 7;
        int b = bg >> 3, g = bg & 7;
        const float* base = x + (long)b * NPIX * CCH + g * GSIZE;
        float s = 0.f, ss = 0.f;
        for (int i = tid; i < 512 * GSIZE; i += blockDim.x) {
            int p = sl * 512 + (i >> 5), c = i & 31;
            float v = base[(long)p * CCH + c];
            s += v; ss += v * v;
        }
        float* sh = &t[0][0];
        #pragma unroll
        for (int o = 16; o > 0; o >>= 1) {
            s  += __shfl_xor_sync(0xffffffffu, s,  o);
            ss += __shfl_xor_sync(0xffffffffu, ss, o);
        }
        int w = tid >> 5, l = tid & 31;
        if (l == 0) { sh[w] = s; sh[8 + w] = ss; }
        __syncthreads();
        if (tid == 0) {
            float S = 0.f, SS = 0.f;
            #pragma unroll
            for (int i = 0; i < 8; i++) { S += sh[i]; SS += sh[8 + i]; }
            g_ps [bg * 8 + sl] = S;
            g_ps2[bg * 8 + sl] = SS;
        }
    } else {
        int tt = id - 256;          // 0..255
        int mat = tt >> 6;          // 0..3
        int w6 = tt & 63;
        int x0 = (w6 & 7) * 32, y0 = (w6 >> 3) * 32;
        const float* src = (mat == 0) ? wq : (mat == 1) ? wk : (mat == 2) ? wv : wp;
        int tx = tid & 31, ty8 = tid >> 5;
        #pragma unroll
        for (int r = 0; r < 4; r++) {
            int ty = ty8 + 8 * r;
            t[ty][tx] = src[(y0 + ty) * CCH + x0 + tx];
        }
        __syncthreads();
        #pragma unroll
        for (int r = 0; r < 4; r++) {
            int ty = ty8 + 8 * r;
            g_wTh[mat * CCH * CCH + (x0 + ty) * CCH + y0 + tx] = __float2half_rn(t[tx][ty]);
        }
    }
}

// ---------------- GroupNorm apply: fp32 in, fp16 out; stats finalized inline ----------------
__global__ void gn_apply(const float* __restrict__ x,
                         const float* __restrict__ gamma,
                         const float* __restrict__ beta) {
    __shared__ float sm[16];
    long i4_0 = (long)blockIdx.x * 256;
    int b = (int)(i4_0 >> 18);          // each block spans one batch (4 rows)
    if (threadIdx.x < 8) {
        int bg = b * 8 + threadIdx.x;
        float S = 0.f, SS = 0.f;
        #pragma unroll
        for (int i = 0; i < 8; i++) { S += g_ps[bg * 8 + i]; SS += g_ps2[bg * 8 + i]; }
        const float invn = 1.0f / (NPIX * GSIZE);
        float mean = S * invn;
        float var  = SS * invn - mean * mean;
        sm[threadIdx.x] = mean;
        sm[8 + threadIdx.x] = rsqrtf(var + 1e-3f);
    }
    __syncthreads();
    long i4 = i4_0 + threadIdx.x;
    float4 xv = ((const float4*)x)[i4];
    int c0 = (int)(i4 & 63) * 4;        // 64 float4 per channel row
    int g = c0 >> 5;
    float m = sm[g], r = sm[8 + g];
    __half2 h0 = __floats2half2_rn((xv.x - m) * r * gamma[c0 + 0] + beta[c0 + 0],
                                   (xv.y - m) * r * gamma[c0 + 1] + beta[c0 + 1]);
    __half2 h1 = __floats2half2_rn((xv.z - m) * r * gamma[c0 + 2] + beta[c0 + 2],
                                   (xv.w - m) * r * gamma[c0 + 3] + beta[c0 + 3]);
    uint2 pk; pk.x = *(unsigned*)&h0; pk.y = *(unsigned*)&h1;
    ((uint2*)g_xnh)[i4] = pk;
}

// ---------------- cp.async / mma / ldmatrix helpers ----------------
__device__ __forceinline__ void cp16g(void* smem, const void* gmem) {
    unsigned s = (unsigned)__cvta_generic_to_shared(smem);
    asm volatile("cp.async.cg.shared.global [%0], [%1], 16;\n" :: "r"(s), "l"(gmem));
}
__device__ __forceinline__ void cp_commit() { asm volatile("cp.async.commit_group;\n"); }
__device__ __forceinline__ void cp_wait0() { asm volatile("cp.async.wait_group 0;\n"); }
__device__ __forceinline__ void cp_wait1() { asm volatile("cp.async.wait_group 1;\n"); }

__device__ __forceinline__ void mma_f16(float* c, const unsigned* a, const unsigned* b) {
    asm volatile("mma.sync.aligned.m16n8k16.row.col.f32.f16.f16.f32 "
        "{%0,%1,%2,%3}, {%4,%5,%6,%7}, {%8,%9}, {%0,%1,%2,%3};"
        : "+f"(c[0]), "+f"(c[1]), "+f"(c[2]), "+f"(c[3])
        : "r"(a[0]), "r"(a[1]), "r"(a[2]), "r"(a[3]), "r"(b[0]), "r"(b[1]));
}
__device__ __forceinline__ void ldsm4(unsigned* r, uint32_t addr) {
    asm volatile("ldmatrix.sync.aligned.m8n8.x4.shared.b16 {%0,%1,%2,%3}, [%4];"
        : "=r"(r[0]), "=r"(r[1]), "=r"(r[2]), "=r"(r[3]) : "r"(addr));
}

// ================= unified fp16 GEMM: C = f(A @ B^T), CTA 128x128, warp 32x64 =================
// A: [M,K] halves lda, B: [N,K] halves ldb (dot over K). Batched via blockIdx.z.
// K-slab = 64 halves, smem pitch 72 halves, 3-stage cp.async pipeline, one bar/slab.
// EPI 0: C(half)  = acc + bias[col]; bias = biasc (z=0) or biasr (z=1)   (Q & K merged)
// EPI 1: C(half)  = acc + biasr[row]                                     (VT projection)
// EPI 2: C(half)  = exp(alpha*acc); Lp[row][j] partial row sums          (scores)
// EPI 3: C(half)  = acc * inv[row]                                       (attn @ V)
// EPI 4: C(float) = acc + biasc[col] + resid[off]                        (final projection)
#define HP 72                       // smem pitch in halves (64 data + 8 pad)
#define SSH (128 * HP)              // halves per matrix per stage (9216)
template<int EPI>
__global__ void __launch_bounds__(256, 2)
hgemm(const __half* __restrict__ A, int lda, long long sAz,
      const __half* __restrict__ B, int ldb, long long sBz,
      void* __restrict__ Cv, int ldc, long long sCz,
      const float* __restrict__ biasc, const float* __restrict__ biasr,
      const float* __restrict__ resid,
      float* __restrict__ Lp, const float* __restrict__ inv,
      float alpha, int K)
{
    extern __shared__ __align__(16) __half dsm[];   // [3][A:SSH | B:SSH]

    A += (long long)blockIdx.z * sAz;
    B += (long long)blockIdx.z * sBz;

    const int tid = threadIdx.x;
    const int w = tid >> 5, lane = tid & 31;
    const int gid = lane >> 2, tig = lane & 3;
    const int wm = (w & 3) * 32;        // 4 m-warps
    const int wn = (w >> 2) * 64;       // 2 n-warps
    const int wg = w >> 2;
    const long long m0 = (long long)blockIdx.y * 128;
    const long long n0 = (long long)blockIdx.x * 128;

    // loader coords: each thread copies 4x16B per matrix per stage
    const int lr = tid >> 1;            // row 0..127
    const int lc = (tid & 1) * 32;      // half-offset 0 or 32
    const __half* Ag = A + (m0 + lr) * lda + lc;
    const __half* Bg = B + (n0 + lr) * (long long)ldb + lc;
    __half* Asd = dsm + lr * HP + lc;   // stage 0 A dst

    // ldmatrix lane address components (in halves)
    const int a_row = wm + (lane & 15);
    const int a_col = (lane >> 4) << 3;
    const int b_row = wn + ((lane >> 4) << 3) + (lane & 7);
    const int b_col = ((lane >> 3) & 1) << 3;
    const uint32_t smB = (uint32_t)__cvta_generic_to_shared(dsm);

    float acc[2][8][4] = {};
    const int KT = K >> 6;              // slabs of 64 halves

    // prologue: slab 0 -> stage 0, slab 1 -> stage 1
    #pragma unroll
    for (int j = 0; j < 4; j++) { cp16g(Asd + 8 * j, Ag + 8 * j); }
    #pragma unroll
    for (int j = 0; j < 4; j++) { cp16g(Asd + SSH + 8 * j, Bg + 8 * j); }
    cp_commit();
    {
        __half* ad = Asd + 2 * SSH;
        #pragma unroll
        for (int j = 0; j < 4; j++) { cp16g(ad + 8 * j, Ag + 64 + 8 * j); }
        #pragma unroll
        for (int j = 0; j < 4; j++) { cp16g(ad + SSH + 8 * j, Bg + 64 + 8 * j); }
        cp_commit();
    }

    int sc = 0;                          // current stage = kt % 3
    for (int kt = 0; kt < KT; kt++) {
        if (kt + 1 < KT) cp_wait1(); else cp_wait0();
        __syncthreads();                 // stage sc ready; stage (kt+2)%3 free
        if (kt + 2 < KT) {
            int s2 = sc + 2; if (s2 >= 3) s2 -= 3;
            long long ko = (long long)(kt + 2) * 64;
            __half* ad = Asd + s2 * (2 * SSH);
            #pragma unroll
            for (int j = 0; j < 4; j++) { cp16g(ad + 8 * j, Ag + ko + 8 * j); }
            #pragma unroll
            for (int j = 0; j < 4; j++) { cp16g(ad + SSH + 8 * j, Bg + ko + 8 * j); }
            cp_commit();
        }
        const uint32_t asb = smB + sc * (4 * SSH);
        const uint32_t bsb = asb + 2 * SSH;
        #pragma unroll
        for (int kk = 0; kk < 64; kk += 16) {
            unsigned a[2][4], b[4][4];
            #pragma unroll
            for (int mt = 0; mt < 2; mt++)
                ldsm4(a[mt], asb + ((a_row + mt * 16) * HP + kk + a_col) * 2);
            #pragma unroll
            for (int p = 0; p < 4; p++)
                ldsm4(b[p], bsb + ((b_row + p * 16) * HP + kk + b_col) * 2);
            #pragma unroll
            for (int mt = 0; mt < 2; mt++)
                #pragma unroll
                for (int nt = 0; nt < 8; nt++)
                    mma_f16(acc[mt][nt], a[mt], &b[nt >> 1][(nt & 1) * 2]);
        }
        if (++sc == 3) sc = 0;
    }

    // ---------------- epilogue ----------------
    #pragma unroll
    for (int mt = 0; mt < 2; mt++) {
        #pragma unroll
        for (int h = 0; h < 2; h++) {
            long long row = m0 + wm + mt * 16 + gid + 8 * h;
            long long cbase = row * ldc + n0 + wn + 2 * tig;
            if (EPI == 2) {
                __half* C = (__half*)Cv + (long long)blockIdx.z * sCz;
                float rowsum = 0.f;
                #pragma unroll
                for (int nt = 0; nt < 8; nt++) {
                    float v0 = __expf(acc[mt][nt][2 * h]     * alpha);
                    float v1 = __expf(acc[mt][nt][2 * h + 1] * alpha);
                    rowsum += v0 + v1;
                    *(__half2*)&C[cbase + nt * 8] = __floats2half2_rn(v0, v1);
                }
                rowsum += __shfl_xor_sync(0xffffffffu, rowsum, 1);
                rowsum += __shfl_xor_sync(0xffffffffu, rowsum, 2);
                if (tig == 0)
                    Lp[(blockIdx.z * (long long)NPIX + row) * 64
                       + blockIdx.x * 2 + wg] = rowsum;
            } else if (EPI == 3) {
                __half* C = (__half*)Cv + (long long)blockIdx.z * sCz;
                float rs = inv[blockIdx.z * (long long)NPIX + row];
                #pragma unroll
                for (int nt = 0; nt < 8; nt++)
                    *(__half2*)&C[cbase + nt * 8] =
                        __floats2half2_rn(acc[mt][nt][2 * h] * rs,
                                          acc[mt][nt][2 * h + 1] * rs);
            } else if (EPI == 4) {
                float* C = (float*)Cv;
                #pragma unroll
                for (int nt = 0; nt < 8; nt++) {
                    long long c0 = n0 + wn + nt * 8 + 2 * tig;
                    long long off = cbase + nt * 8;
                    float v0 = acc[mt][nt][2 * h]     + biasc[c0]     + resid[off];
                    float v1 = acc[mt][nt][2 * h + 1] + biasc[c0 + 1] + resid[off + 1];
                    *(float2*)&C[off] = make_float2(v0, v1);
                }
            } else if (EPI == 0) {
                __half* C = (__half*)Cv + (long long)blockIdx.z * sCz;
                const float* bc = blockIdx.z ? biasr : biasc;   // biasr slot carries bk
                #pragma unroll
                for (int nt = 0; nt < 8; nt++) {
                    long long c0 = n0 + wn + nt * 8 + 2 * tig;
                    *(__half2*)&C[cbase + nt * 8] =
                        __floats2half2_rn(acc[mt][nt][2 * h] + bc[c0],
                                          acc[mt][nt][2 * h + 1] + bc[c0 + 1]);
                }
            } else {  // EPI 1: row bias
                __half* C = (__half*)Cv;
                float rb = biasr[row];
                #pragma unroll
                for (int nt = 0; nt < 8; nt++)
                    *(__half2*)&C[cbase + nt * 8] =
                        __floats2half2_rn(acc[mt][nt][2 * h] + rb,
                                          acc[mt][nt][2 * h + 1] + rb);
            }
        }
    }
}

// ---------------- rowsum inverse: inv[i] = 1 / sum_j Lp[i][j]  (contiguous reads) ----------------
__global__ void rowsum_inv(const float* __restrict__ Lp, float* __restrict__ inv) {
    int i = blockIdx.x * 256 + threadIdx.x;
    const float4* p = (const float4*)(Lp + (long long)i * 64);
    float s = 0.f;
    #pragma unroll
    for (int j = 0; j < 16; j++) {
        float4 v = p[j];
        s += v.x + v.y + v.z + v.w;
    }
    inv[i] = 1.0f / s;
}

// ---------------- launch ----------------
extern "C" void kernel_launch(void* const* d_in, const int* in_sizes, int n_in,
                              void* d_out, int out_size) {
    const float* x     = (const float*)d_in[0];
    const float* gamma = (const float*)d_in[1];
    const float* beta  = (const float*)d_in[2];
    const float* wq    = (const float*)d_in[3];
    const float* bq    = (const float*)d_in[4];
    const float* wk    = (const float*)d_in[5];
    const float* bk    = (const float*)d_in[6];
    const float* wv    = (const float*)d_in[7];
    const float* bv    = (const float*)d_in[8];
    const float* wp    = (const float*)d_in[9];
    const float* bp    = (const float*)d_in[10];
    float* out = (float*)d_out;

    float *Lp, *inv;
    __half *xnh, *qkh, *vth, *oh, *sh, *wTh;
    cudaGetSymbolAddress((void**)&xnh, g_xnh);
    cudaGetSymbolAddress((void**)&qkh, g_qkh);
    cudaGetSymbolAddress((void**)&vth, g_vth);
    cudaGetSymbolAddress((void**)&oh,  g_oh);
    cudaGetSymbolAddress((void**)&sh,  g_sh);
    cudaGetSymbolAddress((void**)&wTh, g_wTh);
    cudaGetSymbolAddress((void**)&Lp,  g_Lp);
    cudaGetSymbolAddress((void**)&inv, g_inv);
    __half* qh = qkh;
    __half* kh = qkh + (long long)MALL * CCH;

    const int SMB = 3 * 2 * SSH * 2;   // 110,592 B dynamic smem (occ 2 = 221 KB/SM)
    cudaFuncSetAttribute(hgemm<0>, cudaFuncAttributeMaxDynamicSharedMemorySize, SMB);
    cudaFuncSetAttribute(hgemm<1>, cudaFuncAttributeMaxDynamicSharedMemorySize, SMB);
    cudaFuncSetAttribute(hgemm<2>, cudaFuncAttributeMaxDynamicSharedMemorySize, SMB);
    cudaFuncSetAttribute(hgemm<3>, cudaFuncAttributeMaxDynamicSharedMemorySize, SMB);
    cudaFuncSetAttribute(hgemm<4>, cudaFuncAttributeMaxDynamicSharedMemorySize, SMB);

    // 1. GN partial stats + weight transposes (one launch)
    gnprep<<<512, 256>>>(x, wq, wk, wv, wp);
    // 2. GN apply (stats finalized inline) -> fp16 xn
    gn_apply<<<(MALL * CCH / 4) / 256, 256>>>(x, gamma, beta);

    // 3. Q & K (merged, grid.z selects), VT (produced transposed)
    hgemm<0><<<dim3(2, 128, 2), 256, SMB>>>(
        xnh, CCH, 0, wTh, CCH, (long long)CCH * CCH, qkh, CCH, (long long)MALL * CCH,
        bq, bk, nullptr, nullptr, nullptr, 1.0f, CCH);
    hgemm<1><<<dim3(MALL / 128, CCH / 128, 1), 256, SMB>>>(
        wTh + 2 * CCH * CCH, CCH, 0, xnh, CCH, 0, vth, MALL, 0,
        nullptr, bv, nullptr, nullptr, nullptr, 1.0f, CCH);

    // 4. S = exp(Q @ K^T / 16) in fp16, plus row-sum partials
    hgemm<2><<<dim3(NPIX / 128, NPIX / 128, BATCH), 256, SMB>>>(
        qh, CCH, (long long)NPIX * CCH,
        kh, CCH, (long long)NPIX * CCH,
        sh, NPIX, (long long)NPIX * NPIX,
        nullptr, nullptr, nullptr, Lp, nullptr, 0.0625f, CCH);

    // 5. inv[row] = 1 / rowsum
    rowsum_inv<<<MALL / 256, 256>>>(Lp, inv);

    // 6. O = (S @ V) * inv  -> fp16   (K = 4096)
    hgemm<3><<<dim3(CCH / 128, NPIX / 128, BATCH), 256, SMB>>>(
        sh, NPIX, (long long)NPIX * NPIX,
        vth, MALL, (long long)NPIX,
        oh, CCH, (long long)NPIX * CCH,
        nullptr, nullptr, nullptr, nullptr, inv, 1.0f, NPIX);

    // 7. y = x + O @ wp + bp   (fp32 out)
    hgemm<4><<<dim3(2, 128, 1), 256, SMB>>>(
        oh, CCH, 0, wTh + 3 * CCH * CCH, CCH, 0, out, CCH, 0,
        bp, nullptr, x, nullptr, nullptr, 1.0f, CCH);
}

// round 16
// speedup vs baseline: 1.0394x; 1.0113x over previous
#include <cuda_runtime.h>
#include <cuda_fp16.h>
#include <cstdint>

// Problem constants (fixed shapes from reference)
#define BATCH   4
#define NPIX    4096          // H*W = 64*64
#define CCH     256
#define GRP     8
#define GSIZE   32            // CCH / GRP
#define MALL    16384         // BATCH * NPIX

// -------- scratch (static device globals; no allocation) --------
__device__ float g_ps [32 * 8];                           // GN partial sums
__device__ float g_ps2[32 * 8];                           // GN partial sumsq
__device__ __half g_xnh[MALL * CCH];
__device__ __half g_qkh[2 * MALL * CCH];                  // Q then K (fp16)
__device__ __half g_vth[CCH * MALL];                      // V transposed (fp16): [256][16384]
__device__ __half g_oh[MALL * CCH];                       // attention output (fp16)
__device__ __half g_sh[(long long)BATCH * NPIX * NPIX];   // exp'd scores, fp16 (128 MB)
__device__ __half g_wTh[4 * CCH * CCH];                   // wq^T, wk^T, wv^T, wp^T (fp16)
__device__ float g_Lp[(long long)MALL * 64];              // row-sum partials [16384][64]

// ---------------- combined prep: GN partial stats + weight transposes ----------------
__global__ void gnprep(const float* __restrict__ x,
                       const float* __restrict__ wq, const float* __restrict__ wk,
                       const float* __restrict__ wv, const float* __restrict__ wp) {
    __shared__ float t[32][33];
    int id = blockIdx.x;
    int tid = threadIdx.x;
    if (id < 256) {
        int bg = id >> 3, sl = id & 7;
        int b = bg >> 3, g = bg & 7;
        const float* base = x + (long)b * NPIX * CCH + g * GSIZE;
        float s = 0.f, ss = 0.f;
        for (int i = tid; i < 512 * GSIZE; i += blockDim.x) {
            int p = sl * 512 + (i >> 5), c = i & 31;
            float v = base[(long)p * CCH + c];
            s += v; ss += v * v;
        }
        float* sh = &t[0][0];
        #pragma unroll
        for (int o = 16; o > 0; o >>= 1) {
            s  += __shfl_xor_sync(0xffffffffu, s,  o);
            ss += __shfl_xor_sync(0xffffffffu, ss, o);
        }
        int w = tid >> 5, l = tid & 31;
        if (l == 0) { sh[w] = s; sh[8 + w] = ss; }
        __syncthreads();
        if (tid == 0) {
            float S = 0.f, SS = 0.f;
            #pragma unroll
            for (int i = 0; i < 8; i++) { S += sh[i]; SS += sh[8 + i]; }
            g_ps [bg * 8 + sl] = S;
            g_ps2[bg * 8 + sl] = SS;
        }
    } else {
        int tt = id - 256;          // 0..255
        int mat = tt >> 6;          // 0..3
        int w6 = tt & 63;
        int x0 = (w6 & 7) * 32, y0 = (w6 >> 3) * 32;
        const float* src = (mat == 0) ? wq : (mat == 1) ? wk : (mat == 2) ? wv : wp;
        int tx = tid & 31, ty8 = tid >> 5;
        #pragma unroll
        for (int r = 0; r < 4; r++) {
            int ty = ty8 + 8 * r;
            t[ty][tx] = src[(y0 + ty) * CCH + x0 + tx];
        }
        __syncthreads();
        #pragma unroll
        for (int r = 0; r < 4; r++) {
            int ty = ty8 + 8 * r;
            g_wTh[mat * CCH * CCH + (x0 + ty) * CCH + y0 + tx] = __float2half_rn(t[tx][ty]);
        }
    }
}

// ---------------- GroupNorm apply: fp32 in, fp16 out; stats finalized inline ----------------
__global__ void gn_apply(const float* __restrict__ x,
                         const float* __restrict__ gamma,
                         const float* __restrict__ beta) {
    __shared__ float sm[16];
    long i4_0 = (long)blockIdx.x * 256;
    int b = (int)(i4_0 >> 18);          // each block spans one batch
    if (threadIdx.x < 8) {
        int bg = b * 8 + threadIdx.x;
        float S = 0.f, SS = 0.f;
        #pragma unroll
        for (int i = 0; i < 8; i++) { S += g_ps[bg * 8 + i]; SS += g_ps2[bg * 8 + i]; }
        const float invn = 1.0f / (NPIX * GSIZE);
        float mean = S * invn;
        float var  = SS * invn - mean * mean;
        sm[threadIdx.x] = mean;
        sm[8 + threadIdx.x] = rsqrtf(var + 1e-3f);
    }
    __syncthreads();
    long i4 = i4_0 + threadIdx.x;
    float4 xv = ((const float4*)x)[i4];
    int c0 = (int)(i4 & 63) * 4;
    int g = c0 >> 5;
    float m = sm[g], r = sm[8 + g];
    __half2 h0 = __floats2half2_rn((xv.x - m) * r * gamma[c0 + 0] + beta[c0 + 0],
                                   (xv.y - m) * r * gamma[c0 + 1] + beta[c0 + 1]);
    __half2 h1 = __floats2half2_rn((xv.z - m) * r * gamma[c0 + 2] + beta[c0 + 2],
                                   (xv.w - m) * r * gamma[c0 + 3] + beta[c0 + 3]);
    uint2 pk; pk.x = *(unsigned*)&h0; pk.y = *(unsigned*)&h1;
    ((uint2*)g_xnh)[i4] = pk;
}

// ---------------- cp.async / mma / ldmatrix helpers ----------------
__device__ __forceinline__ void cp16g(void* smem, const void* gmem) {
    unsigned s = (unsigned)__cvta_generic_to_shared(smem);
    asm volatile("cp.async.cg.shared.global [%0], [%1], 16;\n" :: "r"(s), "l"(gmem));
}
__device__ __forceinline__ void cp_commit() { asm volatile("cp.async.commit_group;\n"); }
__device__ __forceinline__ void cp_wait0() { asm volatile("cp.async.wait_group 0;\n"); }
__device__ __forceinline__ void cp_wait1() { asm volatile("cp.async.wait_group 1;\n"); }

__device__ __forceinline__ void mma_f16(float* c, const unsigned* a, const unsigned* b) {
    asm volatile("mma.sync.aligned.m16n8k16.row.col.f32.f16.f16.f32 "
        "{%0,%1,%2,%3}, {%4,%5,%6,%7}, {%8,%9}, {%0,%1,%2,%3};"
        : "+f"(c[0]), "+f"(c[1]), "+f"(c[2]), "+f"(c[3])
        : "r"(a[0]), "r"(a[1]), "r"(a[2]), "r"(a[3]), "r"(b[0]), "r"(b[1]));
}
__device__ __forceinline__ void ldsm4(unsigned* r, uint32_t addr) {
    asm volatile("ldmatrix.sync.aligned.m8n8.x4.shared.b16 {%0,%1,%2,%3}, [%4];"
        : "=r"(r[0]), "=r"(r[1]), "=r"(r[2]), "=r"(r[3]) : "r"(addr));
}

#define HP 72                       // smem pitch in halves (64 data + 8 pad)
#define SSH (128 * HP)              // halves per matrix per stage (9216)

// ================= merged projection kernel: QK (blocks 0..511) + VT (512..767) ================
// All sub-GEMMs: C = A @ B^T (+bias), lda = ldb = 256, K = 256 (4 slabs).
__global__ void __launch_bounds__(256, 2)
proj_all(const __half* __restrict__ xnh, const __half* __restrict__ wTh,
         __half* __restrict__ qkh, __half* __restrict__ vth,
         const float* __restrict__ bq, const float* __restrict__ bk,
         const float* __restrict__ bv)
{
    extern __shared__ __align__(16) __half dsm[];   // [3][A:SSH | B:SSH]

    const int id = blockIdx.x;
    const bool isVT = (id >= 512);
    const __half* A;
    const __half* B;
    __half* C;
    const float* biasc = nullptr;
    long long m0, n0;
    int ldc;
    if (!isVT) {
        int z = id >> 8, rem = id & 255;
        int bx = rem >> 7, by = rem & 127;
        A = xnh;
        B = wTh + z * (CCH * CCH);
        C = qkh + (long long)z * MALL * CCH;
        ldc = CCH;
        m0 = (long long)by * 128;
        n0 = (long long)bx * 128;
        biasc = z ? bk : bq;
    } else {
        int rem = id - 512;
        int bx = rem >> 1, by = rem & 1;
        A = wTh + 2 * CCH * CCH;
        B = xnh;
        C = vth;
        ldc = MALL;
        m0 = (long long)by * 128;
        n0 = (long long)bx * 128;
    }

    const int tid = threadIdx.x;
    const int w = tid >> 5, lane = tid & 31;
    const int gid = lane >> 2, tig = lane & 3;
    const int wm = (w & 3) * 32;
    const int wn = (w >> 2) * 64;

    const int lr = tid >> 1;
    const int lc = (tid & 1) * 32;
    const __half* Ag = A + (m0 + lr) * CCH + lc;
    const __half* Bg = B + (n0 + lr) * CCH + lc;
    __half* Asd = dsm + lr * HP + lc;

    const int a_row = wm + (lane & 15);
    const int a_col = (lane >> 4) << 3;
    const int b_row = wn + ((lane >> 4) << 3) + (lane & 7);
    const int b_col = ((lane >> 3) & 1) << 3;
    const uint32_t smB = (uint32_t)__cvta_generic_to_shared(dsm);

    float acc[2][8][4] = {};
    const int KT = 4;   // K = 256

    #pragma unroll
    for (int j = 0; j < 4; j++) { cp16g(Asd + 8 * j, Ag + 8 * j); }
    #pragma unroll
    for (int j = 0; j < 4; j++) { cp16g(Asd + SSH + 8 * j, Bg + 8 * j); }
    cp_commit();
    {
        __half* ad = Asd + 2 * SSH;
        #pragma unroll
        for (int j = 0; j < 4; j++) { cp16g(ad + 8 * j, Ag + 64 + 8 * j); }
        #pragma unroll
        for (int j = 0; j < 4; j++) { cp16g(ad + SSH + 8 * j, Bg + 64 + 8 * j); }
        cp_commit();
    }

    int sc = 0;
    for (int kt = 0; kt < KT; kt++) {
        if (kt + 1 < KT) cp_wait1(); else cp_wait0();
        __syncthreads();
        if (kt + 2 < KT) {
            int s2 = sc + 2; if (s2 >= 3) s2 -= 3;
            long long ko = (long long)(kt + 2) * 64;
            __half* ad = Asd + s2 * (2 * SSH);
            #pragma unroll
            for (int j = 0; j < 4; j++) { cp16g(ad + 8 * j, Ag + ko + 8 * j); }
            #pragma unroll
            for (int j = 0; j < 4; j++) { cp16g(ad + SSH + 8 * j, Bg + ko + 8 * j); }
            cp_commit();
        }
        const uint32_t asb = smB + sc * (4 * SSH);
        const uint32_t bsb = asb + 2 * SSH;
        #pragma unroll
        for (int kk = 0; kk < 64; kk += 16) {
            unsigned a[2][4], b[4][4];
            #pragma unroll
            for (int mt = 0; mt < 2; mt++)
                ldsm4(a[mt], asb + ((a_row + mt * 16) * HP + kk + a_col) * 2);
            #pragma unroll
            for (int p = 0; p < 4; p++)
                ldsm4(b[p], bsb + ((b_row + p * 16) * HP + kk + b_col) * 2);
            #pragma unroll
            for (int mt = 0; mt < 2; mt++)
                #pragma unroll
                for (int nt = 0; nt < 8; nt++)
                    mma_f16(acc[mt][nt], a[mt], &b[nt >> 1][(nt & 1) * 2]);
        }
        if (++sc == 3) sc = 0;
    }

    #pragma unroll
    for (int mt = 0; mt < 2; mt++) {
        #pragma unroll
        for (int h = 0; h < 2; h++) {
            long long row = m0 + wm + mt * 16 + gid + 8 * h;
            long long cbase = row * ldc + n0 + wn + 2 * tig;
            if (!isVT) {
                #pragma unroll
                for (int nt = 0; nt < 8; nt++) {
                    long long c0 = n0 + wn + nt * 8 + 2 * tig;
                    *(__half2*)&C[cbase + nt * 8] =
                        __floats2half2_rn(acc[mt][nt][2 * h] + biasc[c0],
                                          acc[mt][nt][2 * h + 1] + biasc[c0 + 1]);
                }
            } else {
                float rb = bv[row];
                #pragma unroll
                for (int nt = 0; nt < 8; nt++)
                    *(__half2*)&C[cbase + nt * 8] =
                        __floats2half2_rn(acc[mt][nt][2 * h] + rb,
                                          acc[mt][nt][2 * h + 1] + rb);
            }
        }
    }
}

// ================= unified fp16 GEMM: C = f(A @ B^T), CTA 128x128, warp 32x64 =================
// EPI 2: C(half)  = exp(alpha*acc); Lp[row][j] partial row sums          (scores)
// EPI 3: C(half)  = acc * inv[row]; inv computed inline from Lp -> smem  (attn @ V)
// EPI 4: C(float) = acc + biasc[col] + resid[off]                        (final projection)
template<int EPI>
__global__ void __launch_bounds__(256, 2)
hgemm(const __half* __restrict__ A, int lda, long long sAz,
      const __half* __restrict__ B, int ldb, long long sBz,
      void* __restrict__ Cv, int ldc, long long sCz,
      const float* __restrict__ biasc, const float* __restrict__ resid,
      float* __restrict__ Lp, float alpha, int K)
{
    extern __shared__ __align__(16) __half dsm[];   // [3][A:SSH | B:SSH] (+ inv[128] for EPI 3)

    A += (long long)blockIdx.z * sAz;
    B += (long long)blockIdx.z * sBz;

    const int tid = threadIdx.x;
    const int w = tid >> 5, lane = tid & 31;
    const int gid = lane >> 2, tig = lane & 3;
    const int wm = (w & 3) * 32;
    const int wn = (w >> 2) * 64;
    const int wg = w >> 2;
    const long long m0 = (long long)blockIdx.y * 128;
    const long long n0 = (long long)blockIdx.x * 128;

    const int lr = tid >> 1;
    const int lc = (tid & 1) * 32;
    const __half* Ag = A + (m0 + lr) * lda + lc;
    const __half* Bg = B + (n0 + lr) * (long long)ldb + lc;
    __half* Asd = dsm + lr * HP + lc;

    const int a_row = wm + (lane & 15);
    const int a_col = (lane >> 4) << 3;
    const int b_row = wn + ((lane >> 4) << 3) + (lane & 7);
    const int b_col = ((lane >> 3) & 1) << 3;
    const uint32_t smB = (uint32_t)__cvta_generic_to_shared(dsm);

    float acc[2][8][4] = {};
    const int KT = K >> 6;

    // prologue: slab 0 -> stage 0, slab 1 -> stage 1
    #pragma unroll
    for (int j = 0; j < 4; j++) { cp16g(Asd + 8 * j, Ag + 8 * j); }
    #pragma unroll
    for (int j = 0; j < 4; j++) { cp16g(Asd + SSH + 8 * j, Bg + 8 * j); }
    cp_commit();
    {
        __half* ad = Asd + 2 * SSH;
        #pragma unroll
        for (int j = 0; j < 4; j++) { cp16g(ad + 8 * j, Ag + 64 + 8 * j); }
        #pragma unroll
        for (int j = 0; j < 4; j++) { cp16g(ad + SSH + 8 * j, Bg + 64 + 8 * j); }
        cp_commit();
    }

    // EPI 3: compute 1/rowsum for this CTA's 128 rows while cp.asyncs fly
    if (EPI == 3) {
        float* sminv = (float*)(dsm + 6 * SSH);
        if (tid < 128) {
            const float4* p = (const float4*)(Lp +
                (blockIdx.z * (long long)NPIX + m0 + tid) * 64);
            float s = 0.f;
            #pragma unroll
            for (int j = 0; j < 16; j++) {
                float4 v = p[j];
                s += v.x + v.y + v.z + v.w;
            }
            sminv[tid] = 1.0f / s;
        }
        __syncthreads();
    }

    int sc = 0;
    for (int kt = 0; kt < KT; kt++) {
        if (kt + 1 < KT) cp_wait1(); else cp_wait0();
        __syncthreads();
        if (kt + 2 < KT) {
            int s2 = sc + 2; if (s2 >= 3) s2 -= 3;
            long long ko = (long long)(kt + 2) * 64;
            __half* ad = Asd + s2 * (2 * SSH);
            #pragma unroll
            for (int j = 0; j < 4; j++) { cp16g(ad + 8 * j, Ag + ko + 8 * j); }
            #pragma unroll
            for (int j = 0; j < 4; j++) { cp16g(ad + SSH + 8 * j, Bg + ko + 8 * j); }
            cp_commit();
        }
        const uint32_t asb = smB + sc * (4 * SSH);
        const uint32_t bsb = asb + 2 * SSH;
        #pragma unroll
        for (int kk = 0; kk < 64; kk += 16) {
            unsigned a[2][4], b[4][4];
            #pragma unroll
            for (int mt = 0; mt < 2; mt++)
                ldsm4(a[mt], asb + ((a_row + mt * 16) * HP + kk + a_col) * 2);
            #pragma unroll
            for (int p = 0; p < 4; p++)
                ldsm4(b[p], bsb + ((b_row + p * 16) * HP + kk + b_col) * 2);
            #pragma unroll
            for (int mt = 0; mt < 2; mt++)
                #pragma unroll
                for (int nt = 0; nt < 8; nt++)
                    mma_f16(acc[mt][nt], a[mt], &b[nt >> 1][(nt & 1) * 2]);
        }
        if (++sc == 3) sc = 0;
    }

    // ---------------- epilogue ----------------
    #pragma unroll
    for (int mt = 0; mt < 2; mt++) {
        #pragma unroll
        for (int h = 0; h < 2; h++) {
            long long row = m0 + wm + mt * 16 + gid + 8 * h;
            long long cbase = row * ldc + n0 + wn + 2 * tig;
            if (EPI == 2) {
                __half* C = (__half*)Cv + (long long)blockIdx.z * sCz;
                float rowsum = 0.f;
                #pragma unroll
                for (int nt = 0; nt < 8; nt++) {
                    float v0 = __expf(acc[mt][nt][2 * h]     * alpha);
                    float v1 = __expf(acc[mt][nt][2 * h + 1] * alpha);
                    rowsum += v0 + v1;
                    *(__half2*)&C[cbase + nt * 8] = __floats2half2_rn(v0, v1);
                }
                rowsum += __shfl_xor_sync(0xffffffffu, rowsum, 1);
                rowsum += __shfl_xor_sync(0xffffffffu, rowsum, 2);
                if (tig == 0)
                    Lp[(blockIdx.z * (long long)NPIX + row) * 64
                       + blockIdx.x * 2 + wg] = rowsum;
            } else if (EPI == 3) {
                __half* C = (__half*)Cv + (long long)blockIdx.z * sCz;
                const float* sminv = (const float*)(dsm + 6 * SSH);
                float rs = sminv[(int)(row - m0)];
                #pragma unroll
                for (int nt = 0; nt < 8; nt++)
                    *(__half2*)&C[cbase + nt * 8] =
                        __floats2half2_rn(acc[mt][nt][2 * h] * rs,
                                          acc[mt][nt][2 * h + 1] * rs);
            } else {  // EPI 4
                float* C = (float*)Cv;
                #pragma unroll
                for (int nt = 0; nt < 8; nt++) {
                    long long c0 = n0 + wn + nt * 8 + 2 * tig;
                    long long off = cbase + nt * 8;
                    float v0 = acc[mt][nt][2 * h]     + biasc[c0]     + resid[off];
                    float v1 = acc[mt][nt][2 * h + 1] + biasc[c0 + 1] + resid[off + 1];
                    *(float2*)&C[off] = make_float2(v0, v1);
                }
            }
        }
    }
}

// ---------------- launch ----------------
extern "C" void kernel_launch(void* const* d_in, const int* in_sizes, int n_in,
                              void* d_out, int out_size) {
    const float* x     = (const float*)d_in[0];
    const float* gamma = (const float*)d_in[1];
    const float* beta  = (const float*)d_in[2];
    const float* wq    = (const float*)d_in[3];
    const float* bq    = (const float*)d_in[4];
    const float* wk    = (const float*)d_in[5];
    const float* bk    = (const float*)d_in[6];
    const float* wv    = (const float*)d_in[7];
    const float* bv    = (const float*)d_in[8];
    const float* wp    = (const float*)d_in[9];
    const float* bp    = (const float*)d_in[10];
    float* out = (float*)d_out;

    float *Lp;
    __half *xnh, *qkh, *vth, *oh, *sh, *wTh;
    cudaGetSymbolAddress((void**)&xnh, g_xnh);
    cudaGetSymbolAddress((void**)&qkh, g_qkh);
    cudaGetSymbolAddress((void**)&vth, g_vth);
    cudaGetSymbolAddress((void**)&oh,  g_oh);
    cudaGetSymbolAddress((void**)&sh,  g_sh);
    cudaGetSymbolAddress((void**)&wTh, g_wTh);
    cudaGetSymbolAddress((void**)&Lp,  g_Lp);
    __half* qh = qkh;
    __half* kh = qkh + (long long)MALL * CCH;

    const int SMB  = 3 * 2 * SSH * 2;        // 110,592 B dynamic smem
    const int SMB3 = SMB + 512;              // + inv[128] for EPI 3
    cudaFuncSetAttribute(proj_all, cudaFuncAttributeMaxDynamicSharedMemorySize, SMB);
    cudaFuncSetAttribute(hgemm<2>, cudaFuncAttributeMaxDynamicSharedMemorySize, SMB);
    cudaFuncSetAttribute(hgemm<3>, cudaFuncAttributeMaxDynamicSharedMemorySize, SMB3);
    cudaFuncSetAttribute(hgemm<4>, cudaFuncAttributeMaxDynamicSharedMemorySize, SMB);

    // 1. GN partial stats + weight transposes (one launch)
    gnprep<<<512, 256>>>(x, wq, wk, wv, wp);
    // 2. GN apply (stats finalized inline) -> fp16 xn
    gn_apply<<<(MALL * CCH / 4) / 256, 256>>>(x, gamma, beta);

    // 3. Q, K, VT projections — single merged launch (768 CTAs)
    proj_all<<<768, 256, SMB>>>(xnh, wTh, qkh, vth, bq, bk, bv);

    // 4. S = exp(Q @ K^T / 16) in fp16, plus row-sum partials
    hgemm<2><<<dim3(NPIX / 128, NPIX / 128, BATCH), 256, SMB>>>(
        qh, CCH, (long long)NPIX * CCH,
        kh, CCH, (long long)NPIX * CCH,
        sh, NPIX, (long long)NPIX * NPIX,
        nullptr, nullptr, Lp, 0.0625f, CCH);

    // 5. O = (S @ V) * inv  -> fp16   (K = 4096; inv computed inline from Lp)
    hgemm<3><<<dim3(CCH / 128, NPIX / 128, BATCH), 256, SMB3>>>(
        sh, NPIX, (long long)NPIX * NPIX,
        vth, MALL, (long long)NPIX,
        oh, CCH, (long long)NPIX * CCH,
        nullptr, nullptr, Lp, 1.0f, NPIX);

    // 6. y = x + O @ wp + bp   (fp32 out)
    hgemm<4><<<dim3(2, 128, 1), 256, SMB>>>(
        oh, CCH, 0, wTh + 3 * CCH * CCH, CCH, 0, out, CCH, 0,
        bp, x, nullptr, 1.0f, CCH);
}

// round 17
// speedup vs baseline: 1.0585x; 1.0184x over previous
#include <cuda_runtime.h>
#include <cuda_fp16.h>
#include <cstdint>

// Problem constants (fixed shapes from reference)
#define BATCH   4
#define NPIX    4096          // H*W = 64*64
#define CCH     256
#define GRP     8
#define GSIZE   32            // CCH / GRP
#define MALL    16384         // BATCH * NPIX

// -------- scratch (static device globals; no allocation) --------
__device__ float g_ps [32 * 8];                           // GN partial sums
__device__ float g_ps2[32 * 8];                           // GN partial sumsq
__device__ __half g_xnh[MALL * CCH];
__device__ __half g_qkh[2 * MALL * CCH];                  // Q then K (fp16)
__device__ __half g_vth[CCH * MALL];                      // V transposed (fp16): [256][16384]
__device__ __half g_oh[MALL * CCH];                       // attention output (fp16)
__device__ __half g_sh[(long long)BATCH * NPIX * NPIX];   // exp'd scores, fp16 (128 MB)
__device__ __half g_wTh[4 * CCH * CCH];                   // wq^T, wk^T, wv^T, wp^T (fp16)
__device__ float g_Lp[(long long)MALL * 64];              // row-sum partials [16384][64]

// ---------------- combined prep: GN partial stats + weight transposes ----------------
__global__ void gnprep(const float* __restrict__ x,
                       const float* __restrict__ wq, const float* __restrict__ wk,
                       const float* __restrict__ wv, const float* __restrict__ wp) {
    __shared__ float t[32][33];
    int id = blockIdx.x;
    int tid = threadIdx.x;
    if (id < 256) {
        int bg = id >> 3, sl = id & 7;
        int b = bg >> 3, g = bg & 7;
        const float* base = x + (long)b * NPIX * CCH + g * GSIZE;
        float s = 0.f, ss = 0.f;
        for (int i = tid; i < 512 * GSIZE; i += blockDim.x) {
            int p = sl * 512 + (i >> 5), c = i & 31;
            float v = base[(long)p * CCH + c];
            s += v; ss += v * v;
        }
        float* sh = &t[0][0];
        #pragma unroll
        for (int o = 16; o > 0; o >>= 1) {
            s  += __shfl_xor_sync(0xffffffffu, s,  o);
            ss += __shfl_xor_sync(0xffffffffu, ss, o);
        }
        int w = tid >> 5, l = tid & 31;
        if (l == 0) { sh[w] = s; sh[8 + w] = ss; }
        __syncthreads();
        if (tid == 0) {
            float S = 0.f, SS = 0.f;
            #pragma unroll
            for (int i = 0; i < 8; i++) { S += sh[i]; SS += sh[8 + i]; }
            g_ps [bg * 8 + sl] = S;
            g_ps2[bg * 8 + sl] = SS;
        }
    } else {
        int tt = id - 256;          // 0..255
        int mat = tt >> 6;          // 0..3
        int w6 = tt & 63;
        int x0 = (w6 & 7) * 32, y0 = (w6 >> 3) * 32;
        const float* src = (mat == 0) ? wq : (mat == 1) ? wk : (mat == 2) ? wv : wp;
        int tx = tid & 31, ty8 = tid >> 5;
        #pragma unroll
        for (int r = 0; r < 4; r++) {
            int ty = ty8 + 8 * r;
            t[ty][tx] = src[(y0 + ty) * CCH + x0 + tx];
        }
        __syncthreads();
        #pragma unroll
        for (int r = 0; r < 4; r++) {
            int ty = ty8 + 8 * r;
            g_wTh[mat * CCH * CCH + (x0 + ty) * CCH + y0 + tx] = __float2half_rn(t[tx][ty]);
        }
    }
}

// ---------------- GroupNorm apply: fp32 in, fp16 out; stats finalized inline ----------------
__global__ void gn_apply(const float* __restrict__ x,
                         const float* __restrict__ gamma,
                         const float* __restrict__ beta) {
    __shared__ float sm[16];
    long i4_0 = (long)blockIdx.x * 256;
    int b = (int)(i4_0 >> 18);          // each block spans one batch
    if (threadIdx.x < 8) {
        int bg = b * 8 + threadIdx.x;
        float S = 0.f, SS = 0.f;
        #pragma unroll
        for (int i = 0; i < 8; i++) { S += g_ps[bg * 8 + i]; SS += g_ps2[bg * 8 + i]; }
        const float invn = 1.0f / (NPIX * GSIZE);
        float mean = S * invn;
        float var  = SS * invn - mean * mean;
        sm[threadIdx.x] = mean;
        sm[8 + threadIdx.x] = rsqrtf(var + 1e-3f);
    }
    __syncthreads();
    long i4 = i4_0 + threadIdx.x;
    float4 xv = ((const float4*)x)[i4];
    int c0 = (int)(i4 & 63) * 4;
    int g = c0 >> 5;
    float m = sm[g], r = sm[8 + g];
    __half2 h0 = __floats2half2_rn((xv.x - m) * r * gamma[c0 + 0] + beta[c0 + 0],
                                   (xv.y - m) * r * gamma[c0 + 1] + beta[c0 + 1]);
    __half2 h1 = __floats2half2_rn((xv.z - m) * r * gamma[c0 + 2] + beta[c0 + 2],
                                   (xv.w - m) * r * gamma[c0 + 3] + beta[c0 + 3]);
    uint2 pk; pk.x = *(unsigned*)&h0; pk.y = *(unsigned*)&h1;
    ((uint2*)g_xnh)[i4] = pk;
}

// ---------------- cp.async / mma / ldmatrix helpers ----------------
__device__ __forceinline__ void cp16g(void* smem, const void* gmem) {
    unsigned s = (unsigned)__cvta_generic_to_shared(smem);
    asm volatile("cp.async.cg.shared.global [%0], [%1], 16;\n" :: "r"(s), "l"(gmem));
}
__device__ __forceinline__ void cp_commit() { asm volatile("cp.async.commit_group;\n"); }
__device__ __forceinline__ void cp_wait0() { asm volatile("cp.async.wait_group 0;\n"); }
__device__ __forceinline__ void cp_wait1() { asm volatile("cp.async.wait_group 1;\n"); }

__device__ __forceinline__ void mma_f16(float* c, const unsigned* a, const unsigned* b) {
    asm volatile("mma.sync.aligned.m16n8k16.row.col.f32.f16.f16.f32 "
        "{%0,%1,%2,%3}, {%4,%5,%6,%7}, {%8,%9}, {%0,%1,%2,%3};"
        : "+f"(c[0]), "+f"(c[1]), "+f"(c[2]), "+f"(c[3])
        : "r"(a[0]), "r"(a[1]), "r"(a[2]), "r"(a[3]), "r"(b[0]), "r"(b[1]));
}
// f16-accumulator variant: acc = 2 b32 regs (4 halves); rows gid/gid+8, cols 2tig..
__device__ __forceinline__ void mma_f16h(unsigned* c, const unsigned* a, const unsigned* b) {
    asm volatile("mma.sync.aligned.m16n8k16.row.col.f16.f16.f16.f16 "
        "{%0,%1}, {%2,%3,%4,%5}, {%6,%7}, {%0,%1};"
        : "+r"(c[0]), "+r"(c[1])
        : "r"(a[0]), "r"(a[1]), "r"(a[2]), "r"(a[3]), "r"(b[0]), "r"(b[1]));
}
__device__ __forceinline__ void ldsm4(unsigned* r, uint32_t addr) {
    asm volatile("ldmatrix.sync.aligned.m8n8.x4.shared.b16 {%0,%1,%2,%3}, [%4];"
        : "=r"(r[0]), "=r"(r[1]), "=r"(r[2]), "=r"(r[3]) : "r"(addr));
}

#define HP 72                       // smem pitch in halves (64 data + 8 pad)
#define SSH (128 * HP)              // halves per matrix per stage (9216)

// ================= merged projection kernel: QK (blocks 0..511) + VT (512..767) ================
__global__ void __launch_bounds__(256, 2)
proj_all(const __half* __restrict__ xnh, const __half* __restrict__ wTh,
         __half* __restrict__ qkh, __half* __restrict__ vth,
         const float* __restrict__ bq, const float* __restrict__ bk,
         const float* __restrict__ bv)
{
    extern __shared__ __align__(16) __half dsm[];   // [3][A:SSH | B:SSH]

    const int id = blockIdx.x;
    const bool isVT = (id >= 512);
    const __half* A;
    const __half* B;
    __half* C;
    const float* biasc = nullptr;
    long long m0, n0;
    int ldc;
    if (!isVT) {
        int z = id >> 8, rem = id & 255;
        int bx = rem >> 7, by = rem & 127;
        A = xnh;
        B = wTh + z * (CCH * CCH);
        C = qkh + (long long)z * MALL * CCH;
        ldc = CCH;
        m0 = (long long)by * 128;
        n0 = (long long)bx * 128;
        biasc = z ? bk : bq;
    } else {
        int rem = id - 512;
        int bx = rem >> 1, by = rem & 1;
        A = wTh + 2 * CCH * CCH;
        B = xnh;
        C = vth;
        ldc = MALL;
        m0 = (long long)by * 128;
        n0 = (long long)bx * 128;
    }

    const int tid = threadIdx.x;
    const int w = tid >> 5, lane = tid & 31;
    const int gid = lane >> 2, tig = lane & 3;
    const int wm = (w & 3) * 32;
    const int wn = (w >> 2) * 64;

    const int lr = tid >> 1;
    const int lc = (tid & 1) * 32;
    const __half* Ag = A + (m0 + lr) * CCH + lc;
    const __half* Bg = B + (n0 + lr) * CCH + lc;
    __half* Asd = dsm + lr * HP + lc;

    const int a_row = wm + (lane & 15);
    const int a_col = (lane >> 4) << 3;
    const int b_row = wn + ((lane >> 4) << 3) + (lane & 7);
    const int b_col = ((lane >> 3) & 1) << 3;
    const uint32_t smB = (uint32_t)__cvta_generic_to_shared(dsm);

    float acc[2][8][4] = {};
    const int KT = 4;   // K = 256

    #pragma unroll
    for (int j = 0; j < 4; j++) { cp16g(Asd + 8 * j, Ag + 8 * j); }
    #pragma unroll
    for (int j = 0; j < 4; j++) { cp16g(Asd + SSH + 8 * j, Bg + 8 * j); }
    cp_commit();
    {
        __half* ad = Asd + 2 * SSH;
        #pragma unroll
        for (int j = 0; j < 4; j++) { cp16g(ad + 8 * j, Ag + 64 + 8 * j); }
        #pragma unroll
        for (int j = 0; j < 4; j++) { cp16g(ad + SSH + 8 * j, Bg + 64 + 8 * j); }
        cp_commit();
    }

    int sc = 0;
    for (int kt = 0; kt < KT; kt++) {
        if (kt + 1 < KT) cp_wait1(); else cp_wait0();
        __syncthreads();
        if (kt + 2 < KT) {
            int s2 = sc + 2; if (s2 >= 3) s2 -= 3;
            long long ko = (long long)(kt + 2) * 64;
            __half* ad = Asd + s2 * (2 * SSH);
            #pragma unroll
            for (int j = 0; j < 4; j++) { cp16g(ad + 8 * j, Ag + ko + 8 * j); }
            #pragma unroll
            for (int j = 0; j < 4; j++) { cp16g(ad + SSH + 8 * j, Bg + ko + 8 * j); }
            cp_commit();
        }
        const uint32_t asb = smB + sc * (4 * SSH);
        const uint32_t bsb = asb + 2 * SSH;
        #pragma unroll
        for (int kk = 0; kk < 64; kk += 16) {
            unsigned a[2][4], b[4][4];
            #pragma unroll
            for (int mt = 0; mt < 2; mt++)
                ldsm4(a[mt], asb + ((a_row + mt * 16) * HP + kk + a_col) * 2);
            #pragma unroll
            for (int p = 0; p < 4; p++)
                ldsm4(b[p], bsb + ((b_row + p * 16) * HP + kk + b_col) * 2);
            #pragma unroll
            for (int mt = 0; mt < 2; mt++)
                #pragma unroll
                for (int nt = 0; nt < 8; nt++)
                    mma_f16(acc[mt][nt], a[mt], &b[nt >> 1][(nt & 1) * 2]);
        }
        if (++sc == 3) sc = 0;
    }

    #pragma unroll
    for (int mt = 0; mt < 2; mt++) {
        #pragma unroll
        for (int h = 0; h < 2; h++) {
            long long row = m0 + wm + mt * 16 + gid + 8 * h;
            long long cbase = row * ldc + n0 + wn + 2 * tig;
            if (!isVT) {
                #pragma unroll
                for (int nt = 0; nt < 8; nt++) {
                    long long c0 = n0 + wn + nt * 8 + 2 * tig;
                    *(__half2*)&C[cbase + nt * 8] =
                        __floats2half2_rn(acc[mt][nt][2 * h] + biasc[c0],
                                          acc[mt][nt][2 * h + 1] + biasc[c0 + 1]);
                }
            } else {
                float rb = bv[row];
                #pragma unroll
                for (int nt = 0; nt < 8; nt++)
                    *(__half2*)&C[cbase + nt * 8] =
                        __floats2half2_rn(acc[mt][nt][2 * h] + rb,
                                          acc[mt][nt][2 * h + 1] + rb);
            }
        }
    }
}

// ============ big attention GEMMs: f16 accumulators, 2-stage pipeline, occ 3 ============
// C = f(A @ B^T), CTA 128x128, warp 32x64, 24 warps/SM.
// EPI 2: C(half) = exp(alpha*acc); Lp[row][j] partial row sums          (scores)
// EPI 3: C(half) = acc * inv[row]; inv computed inline from Lp -> smem  (attn @ V)
template<int EPI>
__global__ void __launch_bounds__(256, 3)
hgemm_h(const __half* __restrict__ A, int lda, long long sAz,
        const __half* __restrict__ B, int ldb, long long sBz,
        __half* __restrict__ C, int ldc, long long sCz,
        float* __restrict__ Lp, float alpha, int K)
{
    extern __shared__ __align__(16) __half dsm[];   // [2][A:SSH | B:SSH] (+ inv[128] EPI3)

    A += (long long)blockIdx.z * sAz;
    B += (long long)blockIdx.z * sBz;

    const int tid = threadIdx.x;
    const int w = tid >> 5, lane = tid & 31;
    const int gid = lane >> 2, tig = lane & 3;
    const int wm = (w & 3) * 32;
    const int wn = (w >> 2) * 64;
    const int wg = w >> 2;
    const long long m0 = (long long)blockIdx.y * 128;
    const long long n0 = (long long)blockIdx.x * 128;

    const int lr = tid >> 1;
    const int lc = (tid & 1) * 32;
    const __half* Ag = A + (m0 + lr) * lda + lc;
    const __half* Bg = B + (n0 + lr) * (long long)ldb + lc;
    __half* Asd = dsm + lr * HP + lc;

    const int a_row = wm + (lane & 15);
    const int a_col = (lane >> 4) << 3;
    const int b_row = wn + ((lane >> 4) << 3) + (lane & 7);
    const int b_col = ((lane >> 3) & 1) << 3;
    const uint32_t smB = (uint32_t)__cvta_generic_to_shared(dsm);

    unsigned acc[2][8][2] = {};      // f16x2 accumulators
    const int KT = K >> 6;

    // prologue: slab 0 -> buf 0
    #pragma unroll
    for (int j = 0; j < 4; j++) { cp16g(Asd + 8 * j, Ag + 8 * j); }
    #pragma unroll
    for (int j = 0; j < 4; j++) { cp16g(Asd + SSH + 8 * j, Bg + 8 * j); }
    cp_commit();

    // EPI 3: compute 1/rowsum for this CTA's 128 rows while cp.asyncs fly
    if (EPI == 3) {
        float* sminv = (float*)(dsm + 4 * SSH);
        if (tid < 128) {
            const float4* p = (const float4*)(Lp +
                (blockIdx.z * (long long)NPIX + m0 + tid) * 64);
            float s = 0.f;
            #pragma unroll
            for (int j = 0; j < 16; j++) {
                float4 v = p[j];
                s += v.x + v.y + v.z + v.w;
            }
            sminv[tid] = 1.0f / s;
        }
    }

    for (int kt = 0; kt < KT; kt++) {
        cp_wait0();
        __syncthreads();
        if (kt + 1 < KT) {
            int buf = (kt + 1) & 1;
            long long ko = (long long)(kt + 1) * 64;
            __half* ad = Asd + buf * (2 * SSH);
            #pragma unroll
            for (int j = 0; j < 4; j++) { cp16g(ad + 8 * j, Ag + ko + 8 * j); }
            #pragma unroll
            for (int j = 0; j < 4; j++) { cp16g(ad + SSH + 8 * j, Bg + ko + 8 * j); }
            cp_commit();
        }
        const uint32_t asb = smB + (kt & 1) * (4 * SSH);
        const uint32_t bsb = asb + 2 * SSH;
        #pragma unroll
        for (int kk = 0; kk < 64; kk += 16) {
            unsigned a[2][4], b[4][4];
            #pragma unroll
            for (int mt = 0; mt < 2; mt++)
                ldsm4(a[mt], asb + ((a_row + mt * 16) * HP + kk + a_col) * 2);
            #pragma unroll
            for (int p = 0; p < 4; p++)
                ldsm4(b[p], bsb + ((b_row + p * 16) * HP + kk + b_col) * 2);
            #pragma unroll
            for (int mt = 0; mt < 2; mt++)
                #pragma unroll
                for (int nt = 0; nt < 8; nt++)
                    mma_f16h(acc[mt][nt], a[mt], &b[nt >> 1][(nt & 1) * 2]);
        }
        __syncthreads();
    }

    // ---------------- epilogue ----------------
    C += (long long)blockIdx.z * sCz;
    #pragma unroll
    for (int mt = 0; mt < 2; mt++) {
        #pragma unroll
        for (int h = 0; h < 2; h++) {
            long long row = m0 + wm + mt * 16 + gid + 8 * h;
            long long cbase = row * ldc + n0 + wn + 2 * tig;
            if (EPI == 2) {
                float rowsum = 0.f;
                #pragma unroll
                for (int nt = 0; nt < 8; nt++) {
                    float2 f = __half22float2(*(__half2*)&acc[mt][nt][h]);
                    float v0 = __expf(f.x * alpha);
                    float v1 = __expf(f.y * alpha);
                    rowsum += v0 + v1;
                    *(__half2*)&C[cbase + nt * 8] = __floats2half2_rn(v0, v1);
                }
                rowsum += __shfl_xor_sync(0xffffffffu, rowsum, 1);
                rowsum += __shfl_xor_sync(0xffffffffu, rowsum, 2);
                if (tig == 0)
                    Lp[(blockIdx.z * (long long)NPIX + row) * 64
                       + blockIdx.x * 2 + wg] = rowsum;
            } else {  // EPI 3
                const float* sminv = (const float*)(dsm + 4 * SSH);
                float rs = sminv[(int)(row - m0)];
                #pragma unroll
                for (int nt = 0; nt < 8; nt++) {
                    float2 f = __half22float2(*(__half2*)&acc[mt][nt][h]);
                    *(__half2*)&C[cbase + nt * 8] =
                        __floats2half2_rn(f.x * rs, f.y * rs);
                }
            }
        }
    }
}

// ================= final projection: y = x + O @ wp^T + bp  (f32 acc, 3-stage) ==========
__global__ void __launch_bounds__(256, 2)
hgemm_fin(const __half* __restrict__ A, const __half* __restrict__ B,
          float* __restrict__ C,
          const float* __restrict__ biasc, const float* __restrict__ resid)
{
    extern __shared__ __align__(16) __half dsm[];

    const int tid = threadIdx.x;
    const int w = tid >> 5, lane = tid & 31;
    const int gid = lane >> 2, tig = lane & 3;
    const int wm = (w & 3) * 32;
    const int wn = (w >> 2) * 64;
    const long long m0 = (long long)blockIdx.y * 128;
    const long long n0 = (long long)blockIdx.x * 128;

    const int lr = tid >> 1;
    const int lc = (tid & 1) * 32;
    const __half* Ag = A + (m0 + lr) * CCH + lc;
    const __half* Bg = B + (n0 + lr) * CCH + lc;
    __half* Asd = dsm + lr * HP + lc;

    const int a_row = wm + (lane & 15);
    const int a_col = (lane >> 4) << 3;
    const int b_row = wn + ((lane >> 4) << 3) + (lane & 7);
    const int b_col = ((lane >> 3) & 1) << 3;
    const uint32_t smB = (uint32_t)__cvta_generic_to_shared(dsm);

    float acc[2][8][4] = {};
    const int KT = 4;

    #pragma unroll
    for (int j = 0; j < 4; j++) { cp16g(Asd + 8 * j, Ag + 8 * j); }
    #pragma unroll
    for (int j = 0; j < 4; j++) { cp16g(Asd + SSH + 8 * j, Bg + 8 * j); }
    cp_commit();
    {
        __half* ad = Asd + 2 * SSH;
        #pragma unroll
        for (int j = 0; j < 4; j++) { cp16g(ad + 8 * j, Ag + 64 + 8 * j); }
        #pragma unroll
        for (int j = 0; j < 4; j++) { cp16g(ad + SSH + 8 * j, Bg + 64 + 8 * j); }
        cp_commit();
    }

    int sc = 0;
    for (int kt = 0; kt < KT; kt++) {
        if (kt + 1 < KT) cp_wait1(); else cp_wait0();
        __syncthreads();
        if (kt + 2 < KT) {
            int s2 = sc + 2; if (s2 >= 3) s2 -= 3;
            long long ko = (long long)(kt + 2) * 64;
            __half* ad = Asd + s2 * (2 * SSH);
            #pragma unroll
            for (int j = 0; j < 4; j++) { cp16g(ad + 8 * j, Ag + ko + 8 * j); }
            #pragma unroll
            for (int j = 0; j < 4; j++) { cp16g(ad + SSH + 8 * j, Bg + ko + 8 * j); }
            cp_commit();
        }
        const uint32_t asb = smB + sc * (4 * SSH);
        const uint32_t bsb = asb + 2 * SSH;
        #pragma unroll
        for (int kk = 0; kk < 64; kk += 16) {
            unsigned a[2][4], b[4][4];
            #pragma unroll
            for (int mt = 0; mt < 2; mt++)
                ldsm4(a[mt], asb + ((a_row + mt * 16) * HP + kk + a_col) * 2);
            #pragma unroll
            for (int p = 0; p < 4; p++)
                ldsm4(b[p], bsb + ((b_row + p * 16) * HP + kk + b_col) * 2);
            #pragma unroll
            for (int mt = 0; mt < 2; mt++)
                #pragma unroll
                for (int nt = 0; nt < 8; nt++)
                    mma_f16(acc[mt][nt], a[mt], &b[nt >> 1][(nt & 1) * 2]);
        }
        if (++sc == 3) sc = 0;
    }

    #pragma unroll
    for (int mt = 0; mt < 2; mt++) {
        #pragma unroll
        for (int h = 0; h < 2; h++) {
            long long row = m0 + wm + mt * 16 + gid + 8 * h;
            long long cbase = row * CCH + n0 + wn + 2 * tig;
            #pragma unroll
            for (int nt = 0; nt < 8; nt++) {
                long long c0 = n0 + wn + nt * 8 + 2 * tig;
                long long off = cbase + nt * 8;
                float v0 = acc[mt][nt][2 * h]     + biasc[c0]     + resid[off];
                float v1 = acc[mt][nt][2 * h + 1] + biasc[c0 + 1] + resid[off + 1];
                *(float2*)&C[off] = make_float2(v0, v1);
            }
        }
    }
}

// ---------------- launch ----------------
extern "C" void kernel_launch(void* const* d_in, const int* in_sizes, int n_in,
                              void* d_out, int out_size) {
    const float* x     = (const float*)d_in[0];
    const float* gamma = (const float*)d_in[1];
    const float* beta  = (const float*)d_in[2];
    const float* wq    = (const float*)d_in[3];
    const float* bq    = (const float*)d_in[4];
    const float* wk    = (const float*)d_in[5];
    const float* bk    = (const float*)d_in[6];
    const float* wv    = (const float*)d_in[7];
    const float* bv    = (const float*)d_in[8];
    const float* wp    = (const float*)d_in[9];
    const float* bp    = (const float*)d_in[10];
    float* out = (float*)d_out;

    float *Lp;
    __half *xnh, *qkh, *vth, *oh, *sh, *wTh;
    cudaGetSymbolAddress((void**)&xnh, g_xnh);
    cudaGetSymbolAddress((void**)&qkh, g_qkh);
    cudaGetSymbolAddress((void**)&vth, g_vth);
    cudaGetSymbolAddress((void**)&oh,  g_oh);
    cudaGetSymbolAddress((void**)&sh,  g_sh);
    cudaGetSymbolAddress((void**)&wTh, g_wTh);
    cudaGetSymbolAddress((void**)&Lp,  g_Lp);
    __half* qh = qkh;
    __half* kh = qkh + (long long)MALL * CCH;

    const int SMB  = 3 * 2 * SSH * 2;        // 110,592 B (3-stage kernels, occ 2)
    const int SMH  = 2 * 2 * SSH * 2;        // 73,728 B  (2-stage, occ 3)
    const int SMH3 = SMH + 512;              // + inv[128]
    cudaFuncSetAttribute(proj_all,   cudaFuncAttributeMaxDynamicSharedMemorySize, SMB);
    cudaFuncSetAttribute(hgemm_h<2>, cudaFuncAttributeMaxDynamicSharedMemorySize, SMH);
    cudaFuncSetAttribute(hgemm_h<3>, cudaFuncAttributeMaxDynamicSharedMemorySize, SMH3);
    cudaFuncSetAttribute(hgemm_fin,  cudaFuncAttributeMaxDynamicSharedMemorySize, SMB);

    // 1. GN partial stats + weight transposes (one launch)
    gnprep<<<512, 256>>>(x, wq, wk, wv, wp);
    // 2. GN apply (stats finalized inline) -> fp16 xn
    gn_apply<<<(MALL * CCH / 4) / 256, 256>>>(x, gamma, beta);

    // 3. Q, K, VT projections — single merged launch (768 CTAs)
    proj_all<<<768, 256, SMB>>>(xnh, wTh, qkh, vth, bq, bk, bv);

    // 4. S = exp(Q @ K^T / 16) in fp16 (f16 acc, occ 3), plus row-sum partials
    hgemm_h<2><<<dim3(NPIX / 128, NPIX / 128, BATCH), 256, SMH>>>(
        qh, CCH, (long long)NPIX * CCH,
        kh, CCH, (long long)NPIX * CCH,
        sh, NPIX, (long long)NPIX * NPIX,
        Lp, 0.0625f, CCH);

    // 5. O = (S @ V) * inv  -> fp16   (f16 acc, occ 3; inv inline from Lp)
    hgemm_h<3><<<dim3(CCH / 128, NPIX / 128, BATCH), 256, SMH3>>>(
        sh, NPIX, (long long)NPIX * NPIX,
        vth, MALL, (long long)NPIX,
        oh, CCH, (long long)NPIX * CCH,
        Lp, 1.0f, NPIX);

    // 6. y = x + O @ wp + bp   (fp32 out)
    hgemm_fin<<<dim3(2, 128, 1), 256, SMB>>>(
        oh, wTh + 3 * CCH * CCH, out, bp, x);
}